// round 2
// baseline (speedup 1.0000x reference)
#include <cuda_runtime.h>
#include <cuda_bf16.h>

// Problem constants (fixed shapes per reference)
#define NPTS   65536
#define CCH    512
#define NH     8
#define PW     128
#define DHD    64
#define RPEN   31      // 2*POS_BND+1
#define PBND   15
#define SCALE  0.125f  // 64^-0.5

// Scratch (static device globals; no runtime allocation allowed)
__device__ float g_qkv[(size_t)NPTS * 1536];  // serialized QKV  [N, 3*C]
__device__ float g_att[(size_t)NPTS * CCH];   // serialized attn out [N, C]

// ---------------------------------------------------------------------------
// SGEMM with A-row gather:  C[m][n] = sum_k A[g[m]][k] * B[n][k] + bias[n]
// A: [?, K] row-major, B: [N, K] row-major (i.e. we compute A @ B^T)
// Tiles: 128x128x8, 256 threads, 8x8 per-thread micro-tile.
// ---------------------------------------------------------------------------
__global__ __launch_bounds__(256, 2)
void sgemm_tn_gather(const float* __restrict__ A, const float* __restrict__ B,
                     const float* __restrict__ bias, const int* __restrict__ gidx,
                     float* __restrict__ C, int N, int K)
{
    __shared__ float As[8][132];   // padded: conflict-free transposed stores
    __shared__ float Bs[8][132];

    const int tid = threadIdx.x;
    const int lr  = tid >> 1;          // 0..127  (row within tile for loads)
    const int lc  = (tid & 1) << 2;    // 0 or 4  (k-chunk within BK=8)
    const int m0  = blockIdx.y * 128;
    const int n0  = blockIdx.x * 128;
    const int ty  = tid >> 4;          // 0..15
    const int tx  = tid & 15;          // 0..15

    const int grow = gidx[m0 + lr];
    const float* Ap = A + (size_t)grow * K + lc;
    const float* Bp = B + (size_t)(n0 + lr) * K + lc;

    float acc[8][8];
#pragma unroll
    for (int i = 0; i < 8; i++)
#pragma unroll
        for (int j = 0; j < 8; j++) acc[i][j] = 0.f;

    for (int k0 = 0; k0 < K; k0 += 8) {
        float4 a4 = *(const float4*)(Ap + k0);
        float4 b4 = *(const float4*)(Bp + k0);
        __syncthreads();
        As[lc+0][lr] = a4.x; As[lc+1][lr] = a4.y; As[lc+2][lr] = a4.z; As[lc+3][lr] = a4.w;
        Bs[lc+0][lr] = b4.x; Bs[lc+1][lr] = b4.y; Bs[lc+2][lr] = b4.z; Bs[lc+3][lr] = b4.w;
        __syncthreads();
#pragma unroll
        for (int k = 0; k < 8; k++) {
            float a[8], b[8];
            *(float4*)&a[0] = *(const float4*)&As[k][ty * 8];
            *(float4*)&a[4] = *(const float4*)&As[k][ty * 8 + 4];
            *(float4*)&b[0] = *(const float4*)&Bs[k][tx * 8];
            *(float4*)&b[4] = *(const float4*)&Bs[k][tx * 8 + 4];
#pragma unroll
            for (int i = 0; i < 8; i++)
#pragma unroll
                for (int j = 0; j < 8; j++) acc[i][j] += a[i] * b[j];
        }
    }

    float bv[8];
#pragma unroll
    for (int j = 0; j < 8; j++) bv[j] = bias[n0 + tx * 8 + j];
#pragma unroll
    for (int i = 0; i < 8; i++) {
        float* Cp = C + (size_t)(m0 + ty * 8 + i) * N + n0 + tx * 8;
        float4 o0, o1;
        o0.x = acc[i][0] + bv[0]; o0.y = acc[i][1] + bv[1];
        o0.z = acc[i][2] + bv[2]; o0.w = acc[i][3] + bv[3];
        o1.x = acc[i][4] + bv[4]; o1.y = acc[i][5] + bv[5];
        o1.z = acc[i][6] + bv[6]; o1.w = acc[i][7] + bv[7];
        *(float4*)Cp       = o0;
        *(float4*)(Cp + 4) = o1;
    }
}

// ---------------------------------------------------------------------------
// Attention per (window, head). blockIdx.x = w (0..511), blockIdx.y = h (0..7)
// smem floats: Ks[128*68] | Vs[128*68] | Ps[128*132] (Qs aliases Ps) | rpe[96] | gc[3*128]
// ---------------------------------------------------------------------------
#define SM_K     0
#define SM_V     (128 * 68)
#define SM_P     (2 * 128 * 68)
#define SM_RPE   (SM_P + 128 * 132)
#define SM_GC    (SM_RPE + 96)
#define SM_TOT_F (SM_GC + 3 * 128)
#define ATTN_SMEM_BYTES (SM_TOT_F * 4)

__global__ __launch_bounds__(256, 1)
void attn_kernel(const float* __restrict__ qkv, const int* __restrict__ order,
                 const int* __restrict__ gcoord, const float* __restrict__ rpe,
                 float* __restrict__ outp)
{
    extern __shared__ float smem[];
    float* Ks   = smem + SM_K;
    float* Vs   = smem + SM_V;
    float* Ps   = smem + SM_P;
    float* Qs   = Ps;                 // Q lives in P's region (dead before P written)
    float* rpeS = smem + SM_RPE;
    int*   gcs  = (int*)(smem + SM_GC);   // gcs[a*128 + p]

    const int w    = blockIdx.x;
    const int h    = blockIdx.y;
    const int tid  = threadIdx.x;
    const int wb   = w * PW;

    // Stage Q, K, V rows: qkv[(wb+p)*1536 + mat*512 + h*64 + d]
    for (int i = tid; i < 128 * 16; i += 256) {
        int row = i >> 4;
        int d4  = (i & 15) << 2;
        size_t src = (size_t)(wb + row) * 1536 + h * 64 + d4;
        float4 qv = *(const float4*)(qkv + src);
        float4 kv = *(const float4*)(qkv + src + 512);
        float4 vv = *(const float4*)(qkv + src + 1024);
        *(float4*)&Qs[row * 68 + d4] = qv;
        *(float4*)&Ks[row * 68 + d4] = kv;
        *(float4*)&Vs[row * 68 + d4] = vv;
    }
    for (int i = tid; i < 128; i += 256) {
        int g = order[wb + i];
        gcs[0 * 128 + i] = gcoord[g * 3 + 0];
        gcs[1 * 128 + i] = gcoord[g * 3 + 1];
        gcs[2 * 128 + i] = gcoord[g * 3 + 2];
    }
    for (int i = tid; i < 3 * RPEN; i += 256) rpeS[i] = rpe[i * NH + h];
    __syncthreads();

    const int tx = tid & 15, ty = tid >> 4;
    const int r0 = ty << 3, c0 = tx << 3;

    // S = Q K^T (8x8 per thread, in registers)
    float acc[8][8];
#pragma unroll
    for (int i = 0; i < 8; i++)
#pragma unroll
        for (int j = 0; j < 8; j++) acc[i][j] = 0.f;

    for (int d = 0; d < DHD; d += 4) {
        float4 a[8];
#pragma unroll
        for (int i = 0; i < 8; i++) a[i] = *(const float4*)&Qs[(r0 + i) * 68 + d];
#pragma unroll
        for (int j = 0; j < 8; j++) {
            float4 b = *(const float4*)&Ks[(c0 + j) * 68 + d];
#pragma unroll
            for (int i = 0; i < 8; i++)
                acc[i][j] += a[i].x * b.x + a[i].y * b.y + a[i].z * b.z + a[i].w * b.w;
        }
    }

    // scale + relative-position bias
    int gr0[8], gr1[8], gr2[8], gq0[8], gq1[8], gq2[8];
#pragma unroll
    for (int i = 0; i < 8; i++) {
        gr0[i] = gcs[0 * 128 + r0 + i];
        gr1[i] = gcs[1 * 128 + r0 + i];
        gr2[i] = gcs[2 * 128 + r0 + i];
        gq0[i] = gcs[0 * 128 + c0 + i];
        gq1[i] = gcs[1 * 128 + c0 + i];
        gq2[i] = gcs[2 * 128 + c0 + i];
    }
#pragma unroll
    for (int i = 0; i < 8; i++)
#pragma unroll
        for (int j = 0; j < 8; j++) {
            int d0 = min(max(gr0[i] - gq0[j], -PBND), PBND) + PBND;
            int d1 = min(max(gr1[i] - gq1[j], -PBND), PBND) + PBND + RPEN;
            int d2 = min(max(gr2[i] - gq2[j], -PBND), PBND) + PBND + 2 * RPEN;
            acc[i][j] = acc[i][j] * SCALE + rpeS[d0] + rpeS[d1] + rpeS[d2];
        }

    // softmax over j (row spans 16 threads: a 16-lane warp segment)
#pragma unroll
    for (int i = 0; i < 8; i++) {
        float m = acc[i][0];
#pragma unroll
        for (int j = 1; j < 8; j++) m = fmaxf(m, acc[i][j]);
#pragma unroll
        for (int s = 8; s >= 1; s >>= 1)
            m = fmaxf(m, __shfl_xor_sync(0xffffffffu, m, s, 16));
        float sum = 0.f;
#pragma unroll
        for (int j = 0; j < 8; j++) { acc[i][j] = __expf(acc[i][j] - m); sum += acc[i][j]; }
#pragma unroll
        for (int s = 8; s >= 1; s >>= 1)
            sum += __shfl_xor_sync(0xffffffffu, sum, s, 16);
        float rinv = 1.0f / sum;
#pragma unroll
        for (int j = 0; j < 8; j++) acc[i][j] *= rinv;
    }

    __syncthreads();   // all Q reads done before overwriting aliased P region
#pragma unroll
    for (int i = 0; i < 8; i++) {
        float4 p0 = make_float4(acc[i][0], acc[i][1], acc[i][2], acc[i][3]);
        float4 p1 = make_float4(acc[i][4], acc[i][5], acc[i][6], acc[i][7]);
        *(float4*)&Ps[(r0 + i) * 132 + c0]     = p0;
        *(float4*)&Ps[(r0 + i) * 132 + c0 + 4] = p1;
    }
    __syncthreads();

    // O = P V  (8 rows x 4 cols per thread)
    const int c2 = tx << 2;   // 0..60
    float o[8][4];
#pragma unroll
    for (int i = 0; i < 8; i++)
#pragma unroll
        for (int c = 0; c < 4; c++) o[i][c] = 0.f;

    for (int j = 0; j < PW; j += 4) {
        float4 vv0 = *(const float4*)&Vs[(j + 0) * 68 + c2];
        float4 vv1 = *(const float4*)&Vs[(j + 1) * 68 + c2];
        float4 vv2 = *(const float4*)&Vs[(j + 2) * 68 + c2];
        float4 vv3 = *(const float4*)&Vs[(j + 3) * 68 + c2];
#pragma unroll
        for (int i = 0; i < 8; i++) {
            float4 pp = *(const float4*)&Ps[(r0 + i) * 132 + j];
            o[i][0] += pp.x * vv0.x + pp.y * vv1.x + pp.z * vv2.x + pp.w * vv3.x;
            o[i][1] += pp.x * vv0.y + pp.y * vv1.y + pp.z * vv2.y + pp.w * vv3.y;
            o[i][2] += pp.x * vv0.z + pp.y * vv1.z + pp.z * vv2.z + pp.w * vv3.z;
            o[i][3] += pp.x * vv0.w + pp.y * vv1.w + pp.z * vv2.w + pp.w * vv3.w;
        }
    }
#pragma unroll
    for (int i = 0; i < 8; i++) {
        float4 ov = make_float4(o[i][0], o[i][1], o[i][2], o[i][3]);
        *(float4*)&outp[(size_t)(wb + r0 + i) * CCH + h * 64 + c2] = ov;
    }
}

// ---------------------------------------------------------------------------
extern "C" void kernel_launch(void* const* d_in, const int* in_sizes, int n_in,
                              void* d_out, int out_size)
{
    const float* feat    = (const float*)d_in[0];
    const float* w_qkv   = (const float*)d_in[1];
    const float* b_qkv   = (const float*)d_in[2];
    const float* w_proj  = (const float*)d_in[3];
    const float* b_proj  = (const float*)d_in[4];
    const float* rpe     = (const float*)d_in[5];
    const int*   gcoord  = (const int*)d_in[6];
    const int*   order   = (const int*)d_in[7];
    const int*   inverse = (const int*)d_in[8];
    float*       out     = (float*)d_out;

    const int M = in_sizes[0] / CCH;   // 65536
    const int W = M / PW;              // 512

    float *qkvbuf, *attbuf;
    cudaGetSymbolAddress((void**)&qkvbuf, g_qkv);
    cudaGetSymbolAddress((void**)&attbuf, g_att);

    cudaFuncSetAttribute(attn_kernel, cudaFuncAttributeMaxDynamicSharedMemorySize,
                         ATTN_SMEM_BYTES);

    dim3 blk(256);
    // 1) QKV projection fused with serialized-order gather
    sgemm_tn_gather<<<dim3(1536 / 128, M / 128), blk>>>(
        feat, w_qkv, b_qkv, order, qkvbuf, 1536, CCH);
    // 2) Windowed attention with RPE bias
    attn_kernel<<<dim3(W, NH), blk, ATTN_SMEM_BYTES>>>(
        qkvbuf, order, gcoord, rpe, attbuf);
    // 3) Output projection fused with inverse-order gather
    sgemm_tn_gather<<<dim3(CCH / 128, M / 128), blk>>>(
        attbuf, w_proj, b_proj, inverse, out, CCH, CCH);
}

// round 4
// speedup vs baseline: 1.9321x; 1.9321x over previous
#include <cuda_runtime.h>
#include <cuda_bf16.h>
#include <stdint.h>

// Problem constants (fixed shapes per reference)
#define NPTS   65536
#define CCH    512
#define NH     8
#define PW     128
#define DHD    64
#define RPEN   31
#define PBND   15
#define SCALE  0.125f

// ---------------------------------------------------------------------------
// Static device scratch
// ---------------------------------------------------------------------------
__device__ float         g_qkv[(size_t)NPTS * 1536];   // serialized QKV (f32)
__device__ __nv_bfloat16 g_fhi[(size_t)NPTS * 512];    // feat[order] hi/lo
__device__ __nv_bfloat16 g_flo[(size_t)NPTS * 512];
__device__ __nv_bfloat16 g_ahi[(size_t)NPTS * 512];    // attn-out (point order) hi/lo
__device__ __nv_bfloat16 g_alo[(size_t)NPTS * 512];
__device__ __nv_bfloat16 g_wqh[1536 * 512];
__device__ __nv_bfloat16 g_wql[1536 * 512];
__device__ __nv_bfloat16 g_wph[512 * 512];
__device__ __nv_bfloat16 g_wpl[512 * 512];

// ---------------------------------------------------------------------------
// PTX helpers (sm_100-legal: ldmatrix / mma.sync / cp.async)
// ---------------------------------------------------------------------------
__device__ __forceinline__ uint32_t smem_u32(const void* p) {
    uint32_t a;
    asm("{ .reg .u64 t; cvta.to.shared.u64 t, %1; cvt.u32.u64 %0, t; }"
        : "=r"(a) : "l"(p));
    return a;
}
__device__ __forceinline__ void cp16(uint32_t dst, const void* src) {
    asm volatile("cp.async.cg.shared.global [%0], [%1], 16;"
                 :: "r"(dst), "l"(src) : "memory");
}
__device__ __forceinline__ void cp_commit() {
    asm volatile("cp.async.commit_group;" ::: "memory");
}
template <int N>
__device__ __forceinline__ void cp_wait() {
    asm volatile("cp.async.wait_group %0;" :: "n"(N) : "memory");
}
__device__ __forceinline__ void ldm_x4(uint32_t* r, uint32_t addr) {
    asm volatile("ldmatrix.sync.aligned.m8n8.x4.shared.b16 {%0,%1,%2,%3}, [%4];"
                 : "=r"(r[0]), "=r"(r[1]), "=r"(r[2]), "=r"(r[3]) : "r"(addr));
}
__device__ __forceinline__ void mma16816(float* d, const uint32_t* a, const uint32_t* b) {
    asm volatile(
        "mma.sync.aligned.m16n8k16.row.col.f32.bf16.bf16.f32 "
        "{%0,%1,%2,%3}, {%4,%5,%6,%7}, {%8,%9}, {%0,%1,%2,%3};"
        : "+f"(d[0]), "+f"(d[1]), "+f"(d[2]), "+f"(d[3])
        : "r"(a[0]), "r"(a[1]), "r"(a[2]), "r"(a[3]), "r"(b[0]), "r"(b[1]));
}

// ---------------------------------------------------------------------------
// bf16-split kernels (x = hi + lo)
// ---------------------------------------------------------------------------
__global__ void split_gather_k(const float* __restrict__ src, const int* __restrict__ gidx,
                               __nv_bfloat16* __restrict__ hi, __nv_bfloat16* __restrict__ lo)
{
    int i = blockIdx.x * 256 + threadIdx.x;          // over NPTS*128 float4 groups
    int m = i >> 7;
    int c = (i & 127) << 2;
    float4 v = *(const float4*)(src + (size_t)gidx[m] * 512 + c);
    float xs[4] = {v.x, v.y, v.z, v.w};
    __align__(8) __nv_bfloat16 hb[4], lb[4];
#pragma unroll
    for (int j = 0; j < 4; j++) {
        hb[j] = __float2bfloat16(xs[j]);
        lb[j] = __float2bfloat16(xs[j] - __bfloat162float(hb[j]));
    }
    size_t o = (size_t)m * 512 + c;
    *(uint2*)(hi + o) = *(uint2*)hb;
    *(uint2*)(lo + o) = *(uint2*)lb;
}

__global__ void split_plain_k(const float* __restrict__ src,
                              __nv_bfloat16* __restrict__ hi, __nv_bfloat16* __restrict__ lo,
                              int n4)
{
    int i = blockIdx.x * 256 + threadIdx.x;
    if (i >= n4) return;
    float4 v = *(const float4*)(src + (size_t)i * 4);
    float xs[4] = {v.x, v.y, v.z, v.w};
    __align__(8) __nv_bfloat16 hb[4], lb[4];
#pragma unroll
    for (int j = 0; j < 4; j++) {
        hb[j] = __float2bfloat16(xs[j]);
        lb[j] = __float2bfloat16(xs[j] - __bfloat162float(hb[j]));
    }
    size_t o = (size_t)i * 4;
    *(uint2*)(hi + o) = *(uint2*)hb;
    *(uint2*)(lo + o) = *(uint2*)lb;
}

// ---------------------------------------------------------------------------
// mma.sync bf16 3-term GEMM: C[m][n] = sum_k A[m][k]*B[n][k] + bias[n]
// A = Ah+Al, B = Bh+Bl. K=512. CTA tile 128x128, BK=32, 8 warps @ 64x32.
// smem tile rows: 40 bf16 (80B stride) -> ldmatrix conflict-free.
// ---------------------------------------------------------------------------
#define GK       512
#define BK       32
#define NCH      (GK / BK)      // 16
#define TROW_B   80             // bytes per smem tile row
#define TILE_B   (128 * TROW_B) // 10240
#define STAGE_B  (4 * TILE_B)   // 40960
#define GSMEM    (2 * STAGE_B)  // 81920

__global__ __launch_bounds__(256, 2)
void gemm_bf16x3(const __nv_bfloat16* __restrict__ Ah, const __nv_bfloat16* __restrict__ Al,
                 const __nv_bfloat16* __restrict__ Bh, const __nv_bfloat16* __restrict__ Bl,
                 const float* __restrict__ bias, float* __restrict__ C, int Ntot)
{
    extern __shared__ __align__(128) char sm[];
    const uint32_t smb = smem_u32(sm);

    const int tid  = threadIdx.x;
    const int lane = tid & 31;
    const int warp = tid >> 5;
    const int wm   = warp >> 2;          // 0..1 -> m offset 64*wm
    const int wn   = warp & 3;           // 0..3 -> n offset 32*wn
    const int m0   = blockIdx.y * 128;
    const int n0   = blockIdx.x * 128;

    const __nv_bfloat16* gsrc[4] = {
        Ah + (size_t)m0 * GK, Al + (size_t)m0 * GK,
        Bh + (size_t)n0 * GK, Bl + (size_t)n0 * GK
    };

    // -------- stage loader: chunk c -> buffer (c&1) --------
    auto load_stage = [&](int c) {
        const uint32_t sb = smb + (c & 1) * STAGE_B;
#pragma unroll
        for (int t = 0; t < 4; t++) {
            const __nv_bfloat16* g = gsrc[t] + c * BK;
#pragma unroll
            for (int i = 0; i < 2; i++) {
                int idx = i * 256 + tid;       // 0..511
                int r = idx >> 2, s = idx & 3; // row, 16B segment
                cp16(sb + t * TILE_B + r * TROW_B + s * 16,
                     g + (size_t)r * GK + s * 8);
            }
        }
    };

    float acc[4][4][4];
#pragma unroll
    for (int i = 0; i < 4; i++)
#pragma unroll
        for (int j = 0; j < 4; j++)
#pragma unroll
            for (int e = 0; e < 4; e++) acc[i][j][e] = 0.f;

    // per-lane ldmatrix address components
    const int arow  = lane & 15;              // A: row within 16
    const int acolb = (lane >> 4) * 16;       // A: +8 cols (bytes)
    const int brow  = (lane & 7) + (lane >> 4) * 8;  // B: n row within 16 (2 frags)
    const int bkb   = ((lane >> 3) & 1) * 16;        // B: +8 k (bytes)

    load_stage(0);
    cp_commit();

    for (int c = 0; c < NCH; c++) {
        if (c + 1 < NCH) { load_stage(c + 1); cp_commit(); cp_wait<1>(); }
        else             { cp_wait<0>(); }
        __syncthreads();

        const uint32_t sb  = smb + (c & 1) * STAGE_B;
        const uint32_t sAh = sb;
        const uint32_t sAl = sb + TILE_B;
        const uint32_t sBh = sb + 2 * TILE_B;
        const uint32_t sBl = sb + 3 * TILE_B;

#pragma unroll
        for (int ks = 0; ks < 2; ks++) {
            const int kb = ks * 32;  // byte offset of k-step (16 bf16)
            uint32_t ah[4][4], al[4][4], bh[2][4], bl[2][4];
#pragma unroll
            for (int mi = 0; mi < 4; mi++)
                ldm_x4(ah[mi], sAh + (wm * 64 + mi * 16 + arow) * TROW_B + kb + acolb);
#pragma unroll
            for (int jj = 0; jj < 2; jj++)
                ldm_x4(bh[jj], sBh + (wn * 32 + jj * 16 + brow) * TROW_B + kb + bkb);
            // term 1: Ah * Bh
#pragma unroll
            for (int mi = 0; mi < 4; mi++)
#pragma unroll
                for (int nj = 0; nj < 4; nj++)
                    mma16816(acc[mi][nj], ah[mi], &bh[nj >> 1][(nj & 1) * 2]);
            // term 2: Ah * Bl
#pragma unroll
            for (int jj = 0; jj < 2; jj++)
                ldm_x4(bl[jj], sBl + (wn * 32 + jj * 16 + brow) * TROW_B + kb + bkb);
#pragma unroll
            for (int mi = 0; mi < 4; mi++)
#pragma unroll
                for (int nj = 0; nj < 4; nj++)
                    mma16816(acc[mi][nj], ah[mi], &bl[nj >> 1][(nj & 1) * 2]);
            // term 3: Al * Bh
#pragma unroll
            for (int mi = 0; mi < 4; mi++)
                ldm_x4(al[mi], sAl + (wm * 64 + mi * 16 + arow) * TROW_B + kb + acolb);
#pragma unroll
            for (int mi = 0; mi < 4; mi++)
#pragma unroll
                for (int nj = 0; nj < 4; nj++)
                    mma16816(acc[mi][nj], al[mi], &bh[nj >> 1][(nj & 1) * 2]);
        }
        if (c + 1 < NCH) __syncthreads();   // protect buffer before next prefetch
    }

    // -------- epilogue: add bias, store f32 --------
    const int gr  = lane >> 2;
    const int gc  = (lane & 3) * 2;
    float2 bv[4];
#pragma unroll
    for (int nj = 0; nj < 4; nj++) {
        int col = n0 + wn * 32 + nj * 8 + gc;
        bv[nj] = *(const float2*)(bias + col);
    }
#pragma unroll
    for (int mi = 0; mi < 4; mi++) {
        int rowa = m0 + wm * 64 + mi * 16 + gr;
#pragma unroll
        for (int nj = 0; nj < 4; nj++) {
            int col = n0 + wn * 32 + nj * 8 + gc;
            float2 lo = make_float2(acc[mi][nj][0] + bv[nj].x, acc[mi][nj][1] + bv[nj].y);
            float2 hi = make_float2(acc[mi][nj][2] + bv[nj].x, acc[mi][nj][3] + bv[nj].y);
            *(float2*)(C + (size_t)rowa * Ntot + col)       = lo;
            *(float2*)(C + (size_t)(rowa + 8) * Ntot + col) = hi;
        }
    }
}

// ---------------------------------------------------------------------------
// Attention per (window, head) — fp32 SIMT; epilogue splits to bf16 hi/lo and
// scatters through `order` so GEMM3 reads linear rows.
// ---------------------------------------------------------------------------
#define SM_K     0
#define SM_V     (128 * 68)
#define SM_P     (2 * 128 * 68)
#define SM_RPE   (SM_P + 128 * 132)
#define SM_GC    (SM_RPE + 96)
#define SM_ORD   (SM_GC + 3 * 128)
#define SM_TOT_F (SM_ORD + 128)
#define ATTN_SMEM_BYTES (SM_TOT_F * 4)

__global__ __launch_bounds__(256, 1)
void attn_kernel(const float* __restrict__ qkv, const int* __restrict__ order,
                 const int* __restrict__ gcoord, const float* __restrict__ rpe,
                 __nv_bfloat16* __restrict__ ohi, __nv_bfloat16* __restrict__ olo)
{
    extern __shared__ float smem[];
    float* Ks   = smem + SM_K;
    float* Vs   = smem + SM_V;
    float* Ps   = smem + SM_P;
    float* Qs   = Ps;
    float* rpeS = smem + SM_RPE;
    int*   gcs  = (int*)(smem + SM_GC);
    int*   ords = (int*)(smem + SM_ORD);

    const int w   = blockIdx.x;
    const int hh  = blockIdx.y;
    const int tid = threadIdx.x;
    const int wb  = w * PW;

    for (int i = tid; i < 128 * 16; i += 256) {
        int row = i >> 4;
        int d4  = (i & 15) << 2;
        size_t src = (size_t)(wb + row) * 1536 + hh * 64 + d4;
        float4 qv = *(const float4*)(qkv + src);
        float4 kv = *(const float4*)(qkv + src + 512);
        float4 vv = *(const float4*)(qkv + src + 1024);
        *(float4*)&Qs[row * 68 + d4] = qv;
        *(float4*)&Ks[row * 68 + d4] = kv;
        *(float4*)&Vs[row * 68 + d4] = vv;
    }
    for (int i = tid; i < 128; i += 256) {
        int g = order[wb + i];
        ords[i] = g;
        gcs[0 * 128 + i] = gcoord[g * 3 + 0];
        gcs[1 * 128 + i] = gcoord[g * 3 + 1];
        gcs[2 * 128 + i] = gcoord[g * 3 + 2];
    }
    for (int i = tid; i < 3 * RPEN; i += 256) rpeS[i] = rpe[i * NH + hh];
    __syncthreads();

    const int tx = tid & 15, ty = tid >> 4;
    const int r0 = ty << 3, c0 = tx << 3;

    float acc[8][8];
#pragma unroll
    for (int i = 0; i < 8; i++)
#pragma unroll
        for (int j = 0; j < 8; j++) acc[i][j] = 0.f;

    for (int d = 0; d < DHD; d += 4) {
        float4 a[8];
#pragma unroll
        for (int i = 0; i < 8; i++) a[i] = *(const float4*)&Qs[(r0 + i) * 68 + d];
#pragma unroll
        for (int j = 0; j < 8; j++) {
            float4 b = *(const float4*)&Ks[(c0 + j) * 68 + d];
#pragma unroll
            for (int i = 0; i < 8; i++)
                acc[i][j] += a[i].x * b.x + a[i].y * b.y + a[i].z * b.z + a[i].w * b.w;
        }
    }

    int gr0[8], gr1[8], gr2[8], gq0[8], gq1[8], gq2[8];
#pragma unroll
    for (int i = 0; i < 8; i++) {
        gr0[i] = gcs[0 * 128 + r0 + i];
        gr1[i] = gcs[1 * 128 + r0 + i];
        gr2[i] = gcs[2 * 128 + r0 + i];
        gq0[i] = gcs[0 * 128 + c0 + i];
        gq1[i] = gcs[1 * 128 + c0 + i];
        gq2[i] = gcs[2 * 128 + c0 + i];
    }
#pragma unroll
    for (int i = 0; i < 8; i++)
#pragma unroll
        for (int j = 0; j < 8; j++) {
            int d0 = min(max(gr0[i] - gq0[j], -PBND), PBND) + PBND;
            int d1 = min(max(gr1[i] - gq1[j], -PBND), PBND) + PBND + RPEN;
            int d2 = min(max(gr2[i] - gq2[j], -PBND), PBND) + PBND + 2 * RPEN;
            acc[i][j] = acc[i][j] * SCALE + rpeS[d0] + rpeS[d1] + rpeS[d2];
        }

#pragma unroll
    for (int i = 0; i < 8; i++) {
        float m = acc[i][0];
#pragma unroll
        for (int j = 1; j < 8; j++) m = fmaxf(m, acc[i][j]);
#pragma unroll
        for (int s = 8; s >= 1; s >>= 1)
            m = fmaxf(m, __shfl_xor_sync(0xffffffffu, m, s, 16));
        float sum = 0.f;
#pragma unroll
        for (int j = 0; j < 8; j++) { acc[i][j] = __expf(acc[i][j] - m); sum += acc[i][j]; }
#pragma unroll
        for (int s = 8; s >= 1; s >>= 1)
            sum += __shfl_xor_sync(0xffffffffu, sum, s, 16);
        float rinv = 1.0f / sum;
#pragma unroll
        for (int j = 0; j < 8; j++) acc[i][j] *= rinv;
    }

    __syncthreads();
#pragma unroll
    for (int i = 0; i < 8; i++) {
        float4 p0 = make_float4(acc[i][0], acc[i][1], acc[i][2], acc[i][3]);
        float4 p1 = make_float4(acc[i][4], acc[i][5], acc[i][6], acc[i][7]);
        *(float4*)&Ps[(r0 + i) * 132 + c0]     = p0;
        *(float4*)&Ps[(r0 + i) * 132 + c0 + 4] = p1;
    }
    __syncthreads();

    const int c2 = tx << 2;
    float o[8][4];
#pragma unroll
    for (int i = 0; i < 8; i++)
#pragma unroll
        for (int c = 0; c < 4; c++) o[i][c] = 0.f;

    for (int j = 0; j < PW; j += 4) {
        float4 vv0 = *(const float4*)&Vs[(j + 0) * 68 + c2];
        float4 vv1 = *(const float4*)&Vs[(j + 1) * 68 + c2];
        float4 vv2 = *(const float4*)&Vs[(j + 2) * 68 + c2];
        float4 vv3 = *(const float4*)&Vs[(j + 3) * 68 + c2];
#pragma unroll
        for (int i = 0; i < 8; i++) {
            float4 pp = *(const float4*)&Ps[(r0 + i) * 132 + j];
            o[i][0] += pp.x * vv0.x + pp.y * vv1.x + pp.z * vv2.x + pp.w * vv3.x;
            o[i][1] += pp.x * vv0.y + pp.y * vv1.y + pp.z * vv2.y + pp.w * vv3.y;
            o[i][2] += pp.x * vv0.z + pp.y * vv1.z + pp.z * vv2.z + pp.w * vv3.z;
            o[i][3] += pp.x * vv0.w + pp.y * vv1.w + pp.z * vv2.w + pp.w * vv3.w;
        }
    }

    // Epilogue: bf16 split + scatter through order (resolves GEMM3 gather)
#pragma unroll
    for (int i = 0; i < 8; i++) {
        int dst = ords[r0 + i];
        __align__(8) __nv_bfloat16 hb[4], lb[4];
#pragma unroll
        for (int c = 0; c < 4; c++) {
            float x = o[i][c];
            hb[c] = __float2bfloat16(x);
            lb[c] = __float2bfloat16(x - __bfloat162float(hb[c]));
        }
        size_t off = (size_t)dst * 512 + hh * 64 + c2;
        *(uint2*)(ohi + off) = *(uint2*)hb;
        *(uint2*)(olo + off) = *(uint2*)lb;
    }
}

// ---------------------------------------------------------------------------
extern "C" void kernel_launch(void* const* d_in, const int* in_sizes, int n_in,
                              void* d_out, int out_size)
{
    const float* feat    = (const float*)d_in[0];
    const float* w_qkv   = (const float*)d_in[1];
    const float* b_qkv   = (const float*)d_in[2];
    const float* w_proj  = (const float*)d_in[3];
    const float* b_proj  = (const float*)d_in[4];
    const float* rpe     = (const float*)d_in[5];
    const int*   gcoord  = (const int*)d_in[6];
    const int*   order   = (const int*)d_in[7];
    float*       out     = (float*)d_out;

    float *qkvbuf;
    __nv_bfloat16 *fhi, *flo, *ahi, *alo, *wqh, *wql, *wph, *wpl;
    cudaGetSymbolAddress((void**)&qkvbuf, g_qkv);
    cudaGetSymbolAddress((void**)&fhi, g_fhi);
    cudaGetSymbolAddress((void**)&flo, g_flo);
    cudaGetSymbolAddress((void**)&ahi, g_ahi);
    cudaGetSymbolAddress((void**)&alo, g_alo);
    cudaGetSymbolAddress((void**)&wqh, g_wqh);
    cudaGetSymbolAddress((void**)&wql, g_wql);
    cudaGetSymbolAddress((void**)&wph, g_wph);
    cudaGetSymbolAddress((void**)&wpl, g_wpl);

    cudaFuncSetAttribute(gemm_bf16x3, cudaFuncAttributeMaxDynamicSharedMemorySize, GSMEM);
    cudaFuncSetAttribute(attn_kernel, cudaFuncAttributeMaxDynamicSharedMemorySize, ATTN_SMEM_BYTES);

    // 1) bf16 splits (feat gathered into serialized order; weights plain)
    split_gather_k<<<NPTS * 128 / 256, 256>>>(feat, order, fhi, flo);
    split_plain_k<<<(1536 * 512 / 4) / 256, 256>>>(w_qkv, wqh, wql, 1536 * 512 / 4);
    split_plain_k<<<(512 * 512 / 4) / 256, 256>>>(w_proj, wph, wpl, 512 * 512 / 4);

    // 2) QKV projection (mma.sync bf16 x3) -> serialized qkv f32
    gemm_bf16x3<<<dim3(1536 / 128, NPTS / 128), 256, GSMEM>>>(
        fhi, flo, wqh, wql, b_qkv, qkvbuf, 1536);

    // 3) Windowed attention; writes bf16-split output scattered to point order
    attn_kernel<<<dim3(NPTS / PW, NH), 256, ATTN_SMEM_BYTES>>>(
        qkvbuf, order, gcoord, rpe, ahi, alo);

    // 4) Output projection (mma.sync bf16 x3) -> d_out
    gemm_bf16x3<<<dim3(512 / 128, NPTS / 128), 256, GSMEM>>>(
        ahi, alo, wph, wpl, b_proj, out, 512);
}

// round 6
// speedup vs baseline: 2.7722x; 1.4349x over previous
#include <cuda_runtime.h>
#include <cuda_bf16.h>
#include <stdint.h>

#define NPTS   65536
#define CCH    512
#define NH     8
#define PW     128
#define DHD    64
#define RPEN   31
#define PBND   15
#define SCALE  0.125f

// ---------------------------------------------------------------------------
// Static device scratch
// ---------------------------------------------------------------------------
__device__ __nv_bfloat16 g_qhi[(size_t)NPTS * 1536];   // serialized qkv hi/lo
__device__ __nv_bfloat16 g_qlo[(size_t)NPTS * 1536];
__device__ __nv_bfloat16 g_fhi[(size_t)NPTS * 512];    // feat[order] hi/lo
__device__ __nv_bfloat16 g_flo[(size_t)NPTS * 512];
__device__ __nv_bfloat16 g_ahi[(size_t)NPTS * 512];    // attn-out (point order)
__device__ __nv_bfloat16 g_alo[(size_t)NPTS * 512];
__device__ __nv_bfloat16 g_wqh[1536 * 512];
__device__ __nv_bfloat16 g_wql[1536 * 512];
__device__ __nv_bfloat16 g_wph[512 * 512];
__device__ __nv_bfloat16 g_wpl[512 * 512];

// ---------------------------------------------------------------------------
// PTX helpers (sm_100-legal)
// ---------------------------------------------------------------------------
__device__ __forceinline__ uint32_t smem_u32(const void* p) {
    uint32_t a;
    asm("{ .reg .u64 t; cvta.to.shared.u64 t, %1; cvt.u32.u64 %0, t; }"
        : "=r"(a) : "l"(p));
    return a;
}
__device__ __forceinline__ void cp16(uint32_t dst, const void* src) {
    asm volatile("cp.async.cg.shared.global [%0], [%1], 16;"
                 :: "r"(dst), "l"(src) : "memory");
}
__device__ __forceinline__ void cp_commit() {
    asm volatile("cp.async.commit_group;" ::: "memory");
}
template <int N>
__device__ __forceinline__ void cp_wait() {
    asm volatile("cp.async.wait_group %0;" :: "n"(N) : "memory");
}
__device__ __forceinline__ void ldm_x4(uint32_t* r, uint32_t addr) {
    asm volatile("ldmatrix.sync.aligned.m8n8.x4.shared.b16 {%0,%1,%2,%3}, [%4];"
                 : "=r"(r[0]), "=r"(r[1]), "=r"(r[2]), "=r"(r[3]) : "r"(addr));
}
__device__ __forceinline__ void ldm_x4_t(uint32_t* r, uint32_t addr) {
    asm volatile("ldmatrix.sync.aligned.m8n8.x4.trans.shared.b16 {%0,%1,%2,%3}, [%4];"
                 : "=r"(r[0]), "=r"(r[1]), "=r"(r[2]), "=r"(r[3]) : "r"(addr));
}
__device__ __forceinline__ void mma16816(float* d, const uint32_t* a, const uint32_t* b) {
    asm volatile(
        "mma.sync.aligned.m16n8k16.row.col.f32.bf16.bf16.f32 "
        "{%0,%1,%2,%3}, {%4,%5,%6,%7}, {%8,%9}, {%0,%1,%2,%3};"
        : "+f"(d[0]), "+f"(d[1]), "+f"(d[2]), "+f"(d[3])
        : "r"(a[0]), "r"(a[1]), "r"(a[2]), "r"(a[3]), "r"(b[0]), "r"(b[1]));
}

// ---------------------------------------------------------------------------
// bf16-split kernels
// ---------------------------------------------------------------------------
__global__ void split_gather_k(const float* __restrict__ src, const int* __restrict__ gidx,
                               __nv_bfloat16* __restrict__ hi, __nv_bfloat16* __restrict__ lo)
{
    int i = blockIdx.x * 256 + threadIdx.x;
    int m = i >> 7;
    int c = (i & 127) << 2;
    float4 v = *(const float4*)(src + (size_t)gidx[m] * 512 + c);
    float xs[4] = {v.x, v.y, v.z, v.w};
    __align__(8) __nv_bfloat16 hb[4], lb[4];
#pragma unroll
    for (int j = 0; j < 4; j++) {
        hb[j] = __float2bfloat16(xs[j]);
        lb[j] = __float2bfloat16(xs[j] - __bfloat162float(hb[j]));
    }
    size_t o = (size_t)m * 512 + c;
    *(uint2*)(hi + o) = *(uint2*)hb;
    *(uint2*)(lo + o) = *(uint2*)lb;
}

__global__ void split_plain_k(const float* __restrict__ src,
                              __nv_bfloat16* __restrict__ hi, __nv_bfloat16* __restrict__ lo,
                              int n4)
{
    int i = blockIdx.x * 256 + threadIdx.x;
    if (i >= n4) return;
    float4 v = *(const float4*)(src + (size_t)i * 4);
    float xs[4] = {v.x, v.y, v.z, v.w};
    __align__(8) __nv_bfloat16 hb[4], lb[4];
#pragma unroll
    for (int j = 0; j < 4; j++) {
        hb[j] = __float2bfloat16(xs[j]);
        lb[j] = __float2bfloat16(xs[j] - __bfloat162float(hb[j]));
    }
    size_t o = (size_t)i * 4;
    *(uint2*)(hi + o) = *(uint2*)hb;
    *(uint2*)(lo + o) = *(uint2*)lb;
}

// ---------------------------------------------------------------------------
// mma.sync bf16 3-term GEMM. Output either f32 (C) or bf16 hi/lo (Chi/Clo).
// ---------------------------------------------------------------------------
#define GK       512
#define BK       32
#define NCH      (GK / BK)
#define TROW_B   80
#define TILE_B   (128 * TROW_B)
#define STAGE_B  (4 * TILE_B)
#define GSMEM    (2 * STAGE_B)

__global__ __launch_bounds__(256, 2)
void gemm_bf16x3(const __nv_bfloat16* __restrict__ Ah, const __nv_bfloat16* __restrict__ Al,
                 const __nv_bfloat16* __restrict__ Bh, const __nv_bfloat16* __restrict__ Bl,
                 const float* __restrict__ bias, float* __restrict__ C,
                 __nv_bfloat16* __restrict__ Chi, __nv_bfloat16* __restrict__ Clo, int Ntot)
{
    extern __shared__ __align__(128) char sm[];
    const uint32_t smb = smem_u32(sm);

    const int tid  = threadIdx.x;
    const int lane = tid & 31;
    const int warp = tid >> 5;
    const int wm   = warp >> 2;
    const int wn   = warp & 3;
    const int m0   = blockIdx.y * 128;
    const int n0   = blockIdx.x * 128;

    const __nv_bfloat16* gsrc[4] = {
        Ah + (size_t)m0 * GK, Al + (size_t)m0 * GK,
        Bh + (size_t)n0 * GK, Bl + (size_t)n0 * GK
    };

    auto load_stage = [&](int c) {
        const uint32_t sb = smb + (c & 1) * STAGE_B;
#pragma unroll
        for (int t = 0; t < 4; t++) {
            const __nv_bfloat16* g = gsrc[t] + c * BK;
#pragma unroll
            for (int i = 0; i < 2; i++) {
                int idx = i * 256 + tid;
                int r = idx >> 2, s = idx & 3;
                cp16(sb + t * TILE_B + r * TROW_B + s * 16,
                     g + (size_t)r * GK + s * 8);
            }
        }
    };

    float acc[4][4][4];
#pragma unroll
    for (int i = 0; i < 4; i++)
#pragma unroll
        for (int j = 0; j < 4; j++)
#pragma unroll
            for (int e = 0; e < 4; e++) acc[i][j][e] = 0.f;

    const int arow  = lane & 15;
    const int acolb = (lane >> 4) * 16;
    const int brow  = (lane & 7) + (lane >> 4) * 8;
    const int bkb   = ((lane >> 3) & 1) * 16;

    load_stage(0);
    cp_commit();

    for (int c = 0; c < NCH; c++) {
        if (c + 1 < NCH) { load_stage(c + 1); cp_commit(); cp_wait<1>(); }
        else             { cp_wait<0>(); }
        __syncthreads();

        const uint32_t sb  = smb + (c & 1) * STAGE_B;
        const uint32_t sAh = sb;
        const uint32_t sAl = sb + TILE_B;
        const uint32_t sBh = sb + 2 * TILE_B;
        const uint32_t sBl = sb + 3 * TILE_B;

#pragma unroll
        for (int ks = 0; ks < 2; ks++) {
            const int kb = ks * 32;
            uint32_t ah[4][4], al[4][4], bh[2][4], bl[2][4];
#pragma unroll
            for (int mi = 0; mi < 4; mi++)
                ldm_x4(ah[mi], sAh + (wm * 64 + mi * 16 + arow) * TROW_B + kb + acolb);
#pragma unroll
            for (int jj = 0; jj < 2; jj++)
                ldm_x4(bh[jj], sBh + (wn * 32 + jj * 16 + brow) * TROW_B + kb + bkb);
#pragma unroll
            for (int mi = 0; mi < 4; mi++)
#pragma unroll
                for (int nj = 0; nj < 4; nj++)
                    mma16816(acc[mi][nj], ah[mi], &bh[nj >> 1][(nj & 1) * 2]);
#pragma unroll
            for (int jj = 0; jj < 2; jj++)
                ldm_x4(bl[jj], sBl + (wn * 32 + jj * 16 + brow) * TROW_B + kb + bkb);
#pragma unroll
            for (int mi = 0; mi < 4; mi++)
#pragma unroll
                for (int nj = 0; nj < 4; nj++)
                    mma16816(acc[mi][nj], ah[mi], &bl[nj >> 1][(nj & 1) * 2]);
#pragma unroll
            for (int mi = 0; mi < 4; mi++)
                ldm_x4(al[mi], sAl + (wm * 64 + mi * 16 + arow) * TROW_B + kb + acolb);
#pragma unroll
            for (int mi = 0; mi < 4; mi++)
#pragma unroll
                for (int nj = 0; nj < 4; nj++)
                    mma16816(acc[mi][nj], al[mi], &bh[nj >> 1][(nj & 1) * 2]);
        }
        if (c + 1 < NCH) __syncthreads();
    }

    const int gr = lane >> 2;
    const int gc = (lane & 3) * 2;
    float2 bv[4];
#pragma unroll
    for (int nj = 0; nj < 4; nj++)
        bv[nj] = *(const float2*)(bias + n0 + wn * 32 + nj * 8 + gc);

    if (Chi) {
#pragma unroll
        for (int mi = 0; mi < 4; mi++) {
            int rowa = m0 + wm * 64 + mi * 16 + gr;
#pragma unroll
            for (int nj = 0; nj < 4; nj++) {
                int col = n0 + wn * 32 + nj * 8 + gc;
                float v0 = acc[mi][nj][0] + bv[nj].x;
                float v1 = acc[mi][nj][1] + bv[nj].y;
                float v2 = acc[mi][nj][2] + bv[nj].x;
                float v3 = acc[mi][nj][3] + bv[nj].y;
                __nv_bfloat162 h01, h23, l01, l23;
                h01.x = __float2bfloat16(v0); h01.y = __float2bfloat16(v1);
                l01.x = __float2bfloat16(v0 - __bfloat162float(h01.x));
                l01.y = __float2bfloat16(v1 - __bfloat162float(h01.y));
                h23.x = __float2bfloat16(v2); h23.y = __float2bfloat16(v3);
                l23.x = __float2bfloat16(v2 - __bfloat162float(h23.x));
                l23.y = __float2bfloat16(v3 - __bfloat162float(h23.y));
                *(__nv_bfloat162*)(Chi + (size_t)rowa * Ntot + col)       = h01;
                *(__nv_bfloat162*)(Clo + (size_t)rowa * Ntot + col)       = l01;
                *(__nv_bfloat162*)(Chi + (size_t)(rowa + 8) * Ntot + col) = h23;
                *(__nv_bfloat162*)(Clo + (size_t)(rowa + 8) * Ntot + col) = l23;
            }
        }
    } else {
#pragma unroll
        for (int mi = 0; mi < 4; mi++) {
            int rowa = m0 + wm * 64 + mi * 16 + gr;
#pragma unroll
            for (int nj = 0; nj < 4; nj++) {
                int col = n0 + wn * 32 + nj * 8 + gc;
                float2 lo = make_float2(acc[mi][nj][0] + bv[nj].x, acc[mi][nj][1] + bv[nj].y);
                float2 hi = make_float2(acc[mi][nj][2] + bv[nj].x, acc[mi][nj][3] + bv[nj].y);
                *(float2*)(C + (size_t)rowa * Ntot + col)       = lo;
                *(float2*)(C + (size_t)(rowa + 8) * Ntot + col) = hi;
            }
        }
    }
}

// ---------------------------------------------------------------------------
// mma.sync attention per (window, head).
// ---------------------------------------------------------------------------
#define ARS      144                    // smem row stride bytes (72 bf16)
#define AT_B     (128 * ARS)
#define OFF_QH   0
#define OFF_QL   (1 * AT_B)
#define OFF_KH   (2 * AT_B)
#define OFF_KL   (3 * AT_B)
#define OFF_VH   (4 * AT_B)
#define OFF_VL   (5 * AT_B)
#define OFF_RPE  (6 * AT_B)
#define OFF_GC   (OFF_RPE + 96 * 4)
#define OFF_ORD  (OFF_GC + 3 * 128 * 4)
#define ASMEM    (OFF_ORD + 128 * 4)

__global__ __launch_bounds__(256, 1)
void attn_mma(const __nv_bfloat16* __restrict__ qhi, const __nv_bfloat16* __restrict__ qlo,
              const int* __restrict__ order, const int* __restrict__ gcoord,
              const float* __restrict__ rpe,
              __nv_bfloat16* __restrict__ ohi, __nv_bfloat16* __restrict__ olo)
{
    extern __shared__ __align__(128) char sm[];
    const uint32_t smb = smem_u32(sm);
    float* rpeS = (float*)(sm + OFF_RPE);
    int*   gcs  = (int*)(sm + OFF_GC);
    int*   ords = (int*)(sm + OFF_ORD);

    const int w    = blockIdx.x;
    const int hh   = blockIdx.y;
    const int tid  = threadIdx.x;
    const int lane = tid & 31;
    const int wid  = tid >> 5;
    const int wb   = w * PW;

    // ---- stage q/k/v hi+lo via cp.async ----
    const __nv_bfloat16* baseh = qhi + (size_t)wb * 1536 + hh * 64;
    const __nv_bfloat16* basel = qlo + (size_t)wb * 1536 + hh * 64;
    const __nv_bfloat16* srcp[6] = {
        baseh, basel, baseh + 512, basel + 512, baseh + 1024, basel + 1024
    };
#pragma unroll
    for (int m = 0; m < 6; m++) {
        uint32_t dstb = smb + m * AT_B;
#pragma unroll
        for (int i = 0; i < 4; i++) {
            int idx = i * 256 + tid;
            int r = idx >> 3, s = idx & 7;
            cp16(dstb + r * ARS + s * 16, srcp[m] + (size_t)r * 1536 + s * 8);
        }
    }
    cp_commit();

    for (int i = tid; i < 128; i += 256) {
        int g = order[wb + i];
        ords[i] = g;
        gcs[0 * 128 + i] = gcoord[g * 3 + 0];
        gcs[1 * 128 + i] = gcoord[g * 3 + 1];
        gcs[2 * 128 + i] = gcoord[g * 3 + 2];
    }
    for (int i = tid; i < 3 * RPEN; i += 256) rpeS[i] = rpe[i * NH + hh];
    cp_wait<0>();
    __syncthreads();

    const int w16   = wid * 16;
    const int arow  = lane & 15;
    const int acolb = (lane >> 4) * 16;
    const int brow  = (lane & 7) + (lane >> 4) * 8;
    const int bkb   = ((lane >> 3) & 1) * 16;

    // ---- S = scale*QK^T : 3-term ----
    uint32_t qh4[4][4], ql4[4][4];
#pragma unroll
    for (int ks = 0; ks < 4; ks++) {
        ldm_x4(qh4[ks], smb + OFF_QH + (w16 + arow) * ARS + ks * 32 + acolb);
        ldm_x4(ql4[ks], smb + OFF_QL + (w16 + arow) * ARS + ks * 32 + acolb);
    }
    float s[16][4];
#pragma unroll
    for (int nj = 0; nj < 16; nj++)
#pragma unroll
        for (int e = 0; e < 4; e++) s[nj][e] = 0.f;

#pragma unroll
    for (int ks = 0; ks < 4; ks++) {
#pragma unroll
        for (int ng = 0; ng < 8; ng++) {
            uint32_t kh[4], kl[4];
            ldm_x4(kh, smb + OFF_KH + (ng * 16 + brow) * ARS + ks * 32 + bkb);
            ldm_x4(kl, smb + OFF_KL + (ng * 16 + brow) * ARS + ks * 32 + bkb);
            mma16816(s[2 * ng],     qh4[ks], kh + 0);
            mma16816(s[2 * ng + 1], qh4[ks], kh + 2);
            mma16816(s[2 * ng],     qh4[ks], kl + 0);
            mma16816(s[2 * ng + 1], qh4[ks], kl + 2);
            mma16816(s[2 * ng],     ql4[ks], kh + 0);
            mma16816(s[2 * ng + 1], ql4[ks], kh + 2);
        }
    }

    // ---- scale + RPE bias (fragment layout) ----
    const int gr  = lane >> 2;
    const int gc2 = (lane & 3) * 2;
    const int r1  = w16 + gr, r2 = r1 + 8;
    const int qa0 = gcs[0 * 128 + r1], qa1 = gcs[1 * 128 + r1], qa2 = gcs[2 * 128 + r1];
    const int qb0 = gcs[0 * 128 + r2], qb1 = gcs[1 * 128 + r2], qb2 = gcs[2 * 128 + r2];

#pragma unroll
    for (int nj = 0; nj < 16; nj++) {
        int c0 = nj * 8 + gc2;
#pragma unroll
        for (int cc = 0; cc < 2; cc++) {
            int c  = c0 + cc;
            int k0 = gcs[0 * 128 + c], k1 = gcs[1 * 128 + c], k2 = gcs[2 * 128 + c];
            int ia0 = min(max(qa0 - k0, -PBND), PBND) + PBND;
            int ia1 = min(max(qa1 - k1, -PBND), PBND) + PBND + RPEN;
            int ia2 = min(max(qa2 - k2, -PBND), PBND) + PBND + 2 * RPEN;
            int ib0 = min(max(qb0 - k0, -PBND), PBND) + PBND;
            int ib1 = min(max(qb1 - k1, -PBND), PBND) + PBND + RPEN;
            int ib2 = min(max(qb2 - k2, -PBND), PBND) + PBND + 2 * RPEN;
            s[nj][cc]     = s[nj][cc]     * SCALE + rpeS[ia0] + rpeS[ia1] + rpeS[ia2];
            s[nj][2 + cc] = s[nj][2 + cc] * SCALE + rpeS[ib0] + rpeS[ib1] + rpeS[ib2];
        }
    }

    // ---- softmax over keys (rows r1, r2) ----
    float m1 = -1e30f, m2 = -1e30f;
#pragma unroll
    for (int nj = 0; nj < 16; nj++) {
        m1 = fmaxf(m1, fmaxf(s[nj][0], s[nj][1]));
        m2 = fmaxf(m2, fmaxf(s[nj][2], s[nj][3]));
    }
    m1 = fmaxf(m1, __shfl_xor_sync(0xffffffffu, m1, 1));
    m1 = fmaxf(m1, __shfl_xor_sync(0xffffffffu, m1, 2));
    m2 = fmaxf(m2, __shfl_xor_sync(0xffffffffu, m2, 1));
    m2 = fmaxf(m2, __shfl_xor_sync(0xffffffffu, m2, 2));
    float s1 = 0.f, s2 = 0.f;
#pragma unroll
    for (int nj = 0; nj < 16; nj++) {
        s[nj][0] = __expf(s[nj][0] - m1); s1 += s[nj][0];
        s[nj][1] = __expf(s[nj][1] - m1); s1 += s[nj][1];
        s[nj][2] = __expf(s[nj][2] - m2); s2 += s[nj][2];
        s[nj][3] = __expf(s[nj][3] - m2); s2 += s[nj][3];
    }
    s1 += __shfl_xor_sync(0xffffffffu, s1, 1);
    s1 += __shfl_xor_sync(0xffffffffu, s1, 2);
    s2 += __shfl_xor_sync(0xffffffffu, s2, 1);
    s2 += __shfl_xor_sync(0xffffffffu, s2, 2);
    float i1 = 1.0f / s1, i2 = 1.0f / s2;

    // ---- P -> bf16 hi/lo A-fragments (C-frag == A-frag layout) ----
    uint32_t pha[8][4], pla[8][4];
#pragma unroll
    for (int kt = 0; kt < 8; kt++) {
#pragma unroll
        for (int half = 0; half < 2; half++) {
            int f = 2 * kt + half;
            float v0 = s[f][0] * i1, v1 = s[f][1] * i1;
            float v2 = s[f][2] * i2, v3 = s[f][3] * i2;
            __nv_bfloat162 h01, h23, l01, l23;
            h01.x = __float2bfloat16(v0); h01.y = __float2bfloat16(v1);
            l01.x = __float2bfloat16(v0 - __bfloat162float(h01.x));
            l01.y = __float2bfloat16(v1 - __bfloat162float(h01.y));
            h23.x = __float2bfloat16(v2); h23.y = __float2bfloat16(v3);
            l23.x = __float2bfloat16(v2 - __bfloat162float(h23.x));
            l23.y = __float2bfloat16(v3 - __bfloat162float(h23.y));
            pha[kt][0 + 2 * half] = *(uint32_t*)&h01;   // a0/a2: row gr
            pha[kt][1 + 2 * half] = *(uint32_t*)&h23;   // a1/a3: row gr+8
            pla[kt][0 + 2 * half] = *(uint32_t*)&l01;
            pla[kt][1 + 2 * half] = *(uint32_t*)&l23;
        }
    }

    // ---- O = P V : 3-term, V B-frags via ldmatrix.trans ----
    float o[8][4];
#pragma unroll
    for (int nj = 0; nj < 8; nj++)
#pragma unroll
        for (int e = 0; e < 4; e++) o[nj][e] = 0.f;

    const int vrow = ((lane >> 3) & 1) * 8 + (lane & 7);
    const int vcb  = (lane >> 4) * 16;
#pragma unroll
    for (int kt = 0; kt < 8; kt++) {
#pragma unroll
        for (int ng = 0; ng < 4; ng++) {          // 4 groups of 16 dims
            uint32_t vh[4], vl[4];
            ldm_x4_t(vh, smb + OFF_VH + (kt * 16 + vrow) * ARS + ng * 32 + vcb);
            ldm_x4_t(vl, smb + OFF_VL + (kt * 16 + vrow) * ARS + ng * 32 + vcb);
            mma16816(o[2 * ng],     pha[kt], vh + 0);
            mma16816(o[2 * ng + 1], pha[kt], vh + 2);
            mma16816(o[2 * ng],     pha[kt], vl + 0);
            mma16816(o[2 * ng + 1], pha[kt], vl + 2);
            mma16816(o[2 * ng],     pla[kt], vh + 0);
            mma16816(o[2 * ng + 1], pla[kt], vh + 2);
        }
    }

    // ---- epilogue: bf16 split, scatter through order ----
    const int d1 = ords[r1], d2 = ords[r2];
#pragma unroll
    for (int nj = 0; nj < 8; nj++) {
        int col = nj * 8 + gc2;
        size_t o1 = (size_t)d1 * 512 + hh * 64 + col;
        size_t o2 = (size_t)d2 * 512 + hh * 64 + col;
        __nv_bfloat162 h01, h23, l01, l23;
        h01.x = __float2bfloat16(o[nj][0]); h01.y = __float2bfloat16(o[nj][1]);
        l01.x = __float2bfloat16(o[nj][0] - __bfloat162float(h01.x));
        l01.y = __float2bfloat16(o[nj][1] - __bfloat162float(h01.y));
        h23.x = __float2bfloat16(o[nj][2]); h23.y = __float2bfloat16(o[nj][3]);
        l23.x = __float2bfloat16(o[nj][2] - __bfloat162float(h23.x));
        l23.y = __float2bfloat16(o[nj][3] - __bfloat162float(h23.y));
        *(__nv_bfloat162*)(ohi + o1) = h01;
        *(__nv_bfloat162*)(olo + o1) = l01;
        *(__nv_bfloat162*)(ohi + o2) = h23;
        *(__nv_bfloat162*)(olo + o2) = l23;
    }
}

// ---------------------------------------------------------------------------
extern "C" void kernel_launch(void* const* d_in, const int* in_sizes, int n_in,
                              void* d_out, int out_size)
{
    const float* feat    = (const float*)d_in[0];
    const float* w_qkv   = (const float*)d_in[1];
    const float* b_qkv   = (const float*)d_in[2];
    const float* w_proj  = (const float*)d_in[3];
    const float* b_proj  = (const float*)d_in[4];
    const float* rpe     = (const float*)d_in[5];
    const int*   gcoord  = (const int*)d_in[6];
    const int*   order   = (const int*)d_in[7];
    float*       out     = (float*)d_out;

    __nv_bfloat16 *qhi, *qlo, *fhi, *flo, *ahi, *alo, *wqh, *wql, *wph, *wpl;
    cudaGetSymbolAddress((void**)&qhi, g_qhi);
    cudaGetSymbolAddress((void**)&qlo, g_qlo);
    cudaGetSymbolAddress((void**)&fhi, g_fhi);
    cudaGetSymbolAddress((void**)&flo, g_flo);
    cudaGetSymbolAddress((void**)&ahi, g_ahi);
    cudaGetSymbolAddress((void**)&alo, g_alo);
    cudaGetSymbolAddress((void**)&wqh, g_wqh);
    cudaGetSymbolAddress((void**)&wql, g_wql);
    cudaGetSymbolAddress((void**)&wph, g_wph);
    cudaGetSymbolAddress((void**)&wpl, g_wpl);

    cudaFuncSetAttribute(gemm_bf16x3, cudaFuncAttributeMaxDynamicSharedMemorySize, GSMEM);
    cudaFuncSetAttribute(attn_mma, cudaFuncAttributeMaxDynamicSharedMemorySize, ASMEM);

    // 1) bf16 splits
    split_gather_k<<<NPTS * 128 / 256, 256>>>(feat, order, fhi, flo);
    split_plain_k<<<(1536 * 512 / 4) / 256, 256>>>(w_qkv, wqh, wql, 1536 * 512 / 4);
    split_plain_k<<<(512 * 512 / 4) / 256, 256>>>(w_proj, wph, wpl, 512 * 512 / 4);

    // 2) QKV projection -> serialized qkv bf16 hi/lo (bias added)
    gemm_bf16x3<<<dim3(1536 / 128, NPTS / 128), 256, GSMEM>>>(
        fhi, flo, wqh, wql, b_qkv, nullptr, qhi, qlo, 1536);

    // 3) mma attention; writes bf16-split output scattered to point order
    attn_mma<<<dim3(NPTS / PW, NH), 256, ASMEM>>>(
        qhi, qlo, order, gcoord, rpe, ahi, alo);

    // 4) Output projection -> f32 d_out
    gemm_bf16x3<<<dim3(512 / 128, NPTS / 128), 256, GSMEM>>>(
        ahi, alo, wph, wpl, b_proj, out, nullptr, nullptr, 512);
}